// round 9
// baseline (speedup 1.0000x reference)
#include <cuda_runtime.h>

// Prediction_65189013618796 — CONVERGED configuration (session best).
// prob: [B=64, 2N=2048] float32. start = prob[:, :N], end = prob[:, N:].
// band 0 <= j - i <= 15. Inputs uniform[0,1) => non-negative, so:
//   start_position[b,i] = start[b,i] * max(end[b, i..min(i+15,N-1)])
//   end_position[b,j]   = end[b,j]   * max(start[b, max(j-15,0)..j])
//
// Split-direction kernel: 32768 threads, each produces ONE float4 output
// group for ONE direction. Blocks 0..63 -> forward (start_position),
// blocks 64..127 -> backward (end_position). Uniform per CTA, no divergence.
// Edge padding replicates end[N-1] / start[0] (max-neutral: the clamped
// window always contains that element).
//
// Session finding (R0-R8): kernel is pinned at the per-launch overhead floor
// (T_ovh ~5000 cyc ~= 4.3us ncu); DRAM 1.5%, issue ~6%. All structural
// variants measured 4.3-4.6us ncu; e2e timer is bimodal {~4.6, ~6.9} over
// identical binaries. This exact source holds the best measurements:
// dur_us 4.608 / ncu 4.288us (R8), dur_us 4.672 / ncu 4.384us (R3/R6).

#define NB   64
#define NN   1024
#define NG   (NN / 4)     // 256 float4 groups per row

__global__ __launch_bounds__(256, 8)
void banded_span_kernel(const float* __restrict__ prob, float* __restrict__ out) {
    const int idx = (blockIdx.x & 63) * 256 + threadIdx.x;  // 0..16383
    const int b = idx >> 8;                                 // row 0..63
    const int g = idx & (NG - 1);                           // group 0..255

    const float4* row4 = reinterpret_cast<const float4*>(prob + (size_t)b * 2 * NN);
    float4* o4 = reinterpret_cast<float4*>(out);

    if (blockIdx.x < 64) {
        // ---- forward: start_position[b, 4g..4g+3] ----
        const float4* e4 = row4 + NG;
        float e[20];
        #pragma unroll
        for (int k = 0; k < 5; ++k) {
            int gg = g + k;
            float4 v = e4[gg > NG - 1 ? NG - 1 : gg];
            if (gg > NG - 1) { v.x = v.w; v.y = v.w; v.z = v.w; }
            e[4 * k + 0] = v.x; e[4 * k + 1] = v.y;
            e[4 * k + 2] = v.z; e[4 * k + 3] = v.w;
        }
        float4 sv = row4[g];  // start point values

        // shared core max(e[3..15]), tree-shaped for shorter dep chain
        float c01 = fmaxf(e[3], e[4]),  c23 = fmaxf(e[5], e[6]);
        float c45 = fmaxf(e[7], e[8]),  c67 = fmaxf(e[9], e[10]);
        float c89 = fmaxf(e[11], e[12]), cab = fmaxf(e[13], e[14]);
        float ce = fmaxf(fmaxf(fmaxf(c01, c23), fmaxf(c45, c67)),
                         fmaxf(fmaxf(c89, cab), e[15]));
        float fe0 = fmaxf(fmaxf(ce, e[0]),  fmaxf(e[1],  e[2]));
        float fe1 = fmaxf(fmaxf(ce, e[1]),  fmaxf(e[2],  e[16]));
        float fe2 = fmaxf(fmaxf(ce, e[2]),  fmaxf(e[16], e[17]));
        float fe3 = fmaxf(fmaxf(ce, e[16]), fmaxf(e[17], e[18]));

        o4[(size_t)b * NG + g] =
            make_float4(sv.x * fe0, sv.y * fe1, sv.z * fe2, sv.w * fe3);
    } else {
        // ---- backward: end_position[b, 4g..4g+3] ----
        float s[20];
        #pragma unroll
        for (int k = 0; k < 5; ++k) {
            int gg = g - 4 + k;
            float4 v = row4[gg < 0 ? 0 : gg];
            if (gg < 0) { v.y = v.x; v.z = v.x; v.w = v.x; }
            s[4 * k + 0] = v.x; s[4 * k + 1] = v.y;
            s[4 * k + 2] = v.z; s[4 * k + 3] = v.w;
        }
        float4 ev = row4[NG + g];  // end point values

        // shared core max(s[4..16])
        float c01 = fmaxf(s[4], s[5]),   c23 = fmaxf(s[6], s[7]);
        float c45 = fmaxf(s[8], s[9]),   c67 = fmaxf(s[10], s[11]);
        float c89 = fmaxf(s[12], s[13]), cab = fmaxf(s[14], s[15]);
        float cs = fmaxf(fmaxf(fmaxf(c01, c23), fmaxf(c45, c67)),
                         fmaxf(fmaxf(c89, cab), s[16]));
        float ms0 = fmaxf(fmaxf(cs, s[1]),  fmaxf(s[2],  s[3]));
        float ms1 = fmaxf(fmaxf(cs, s[2]),  fmaxf(s[3],  s[17]));
        float ms2 = fmaxf(fmaxf(cs, s[3]),  fmaxf(s[17], s[18]));
        float ms3 = fmaxf(fmaxf(cs, s[17]), fmaxf(s[18], s[19]));

        o4[(size_t)NB * NG + (size_t)b * NG + g] =
            make_float4(ev.x * ms0, ev.y * ms1, ev.z * ms2, ev.w * ms3);
    }
}

extern "C" void kernel_launch(void* const* d_in, const int* in_sizes, int n_in,
                              void* d_out, int out_size) {
    const float* prob = (const float*)d_in[0];
    float* out = (float*)d_out;
    banded_span_kernel<<<128, 256>>>(prob, out);
}

// round 10
// speedup vs baseline: 1.4795x; 1.4795x over previous
#include <cuda_runtime.h>

// Prediction_65189013618796 — CONVERGED configuration (session best, FINAL).
// prob: [B=64, 2N=2048] float32. start = prob[:, :N], end = prob[:, N:].
// band 0 <= j - i <= 15. Inputs uniform[0,1) => non-negative, so:
//   start_position[b,i] = start[b,i] * max(end[b, i..min(i+15,N-1)])
//   end_position[b,j]   = end[b,j]   * max(start[b, max(j-15,0)..j])
//
// Split-direction kernel: 32768 threads, each produces ONE float4 output
// group for ONE direction. Blocks 0..63 -> forward (start_position),
// blocks 64..127 -> backward (end_position). Uniform per CTA, no divergence.
// Edge padding replicates end[N-1] / start[0] (max-neutral: the clamped
// window always contains that element).
//
// Session finding (R0-R9): kernel is pinned at the per-launch overhead floor
// (~4.2us ncu ~ T_ovh 5000 cyc); DRAM 1.6%, issue 7% — the launch IS the
// kernel. All structural variants (smem+barrier, fat-thread, branch-split,
// 64x512 grid, warp-shuffle halo) measured equal-or-worse. The e2e timer is
// bimodal {~4.6, ~6.9} over identical binaries. This exact source holds ALL
// session-best measurements: ncu {4.160, 4.288, 4.384, 4.384}us,
// dur_us best 4.608.

#define NB   64
#define NN   1024
#define NG   (NN / 4)     // 256 float4 groups per row

__global__ __launch_bounds__(256, 8)
void banded_span_kernel(const float* __restrict__ prob, float* __restrict__ out) {
    const int idx = (blockIdx.x & 63) * 256 + threadIdx.x;  // 0..16383
    const int b = idx >> 8;                                 // row 0..63
    const int g = idx & (NG - 1);                           // group 0..255

    const float4* row4 = reinterpret_cast<const float4*>(prob + (size_t)b * 2 * NN);
    float4* o4 = reinterpret_cast<float4*>(out);

    if (blockIdx.x < 64) {
        // ---- forward: start_position[b, 4g..4g+3] ----
        const float4* e4 = row4 + NG;
        float e[20];
        #pragma unroll
        for (int k = 0; k < 5; ++k) {
            int gg = g + k;
            float4 v = e4[gg > NG - 1 ? NG - 1 : gg];
            if (gg > NG - 1) { v.x = v.w; v.y = v.w; v.z = v.w; }
            e[4 * k + 0] = v.x; e[4 * k + 1] = v.y;
            e[4 * k + 2] = v.z; e[4 * k + 3] = v.w;
        }
        float4 sv = row4[g];  // start point values

        // shared core max(e[3..15]), tree-shaped for shorter dep chain
        float c01 = fmaxf(e[3], e[4]),  c23 = fmaxf(e[5], e[6]);
        float c45 = fmaxf(e[7], e[8]),  c67 = fmaxf(e[9], e[10]);
        float c89 = fmaxf(e[11], e[12]), cab = fmaxf(e[13], e[14]);
        float ce = fmaxf(fmaxf(fmaxf(c01, c23), fmaxf(c45, c67)),
                         fmaxf(fmaxf(c89, cab), e[15]));
        float fe0 = fmaxf(fmaxf(ce, e[0]),  fmaxf(e[1],  e[2]));
        float fe1 = fmaxf(fmaxf(ce, e[1]),  fmaxf(e[2],  e[16]));
        float fe2 = fmaxf(fmaxf(ce, e[2]),  fmaxf(e[16], e[17]));
        float fe3 = fmaxf(fmaxf(ce, e[16]), fmaxf(e[17], e[18]));

        o4[(size_t)b * NG + g] =
            make_float4(sv.x * fe0, sv.y * fe1, sv.z * fe2, sv.w * fe3);
    } else {
        // ---- backward: end_position[b, 4g..4g+3] ----
        float s[20];
        #pragma unroll
        for (int k = 0; k < 5; ++k) {
            int gg = g - 4 + k;
            float4 v = row4[gg < 0 ? 0 : gg];
            if (gg < 0) { v.y = v.x; v.z = v.x; v.w = v.x; }
            s[4 * k + 0] = v.x; s[4 * k + 1] = v.y;
            s[4 * k + 2] = v.z; s[4 * k + 3] = v.w;
        }
        float4 ev = row4[NG + g];  // end point values

        // shared core max(s[4..16])
        float c01 = fmaxf(s[4], s[5]),   c23 = fmaxf(s[6], s[7]);
        float c45 = fmaxf(s[8], s[9]),   c67 = fmaxf(s[10], s[11]);
        float c89 = fmaxf(s[12], s[13]), cab = fmaxf(s[14], s[15]);
        float cs = fmaxf(fmaxf(fmaxf(c01, c23), fmaxf(c45, c67)),
                         fmaxf(fmaxf(c89, cab), s[16]));
        float ms0 = fmaxf(fmaxf(cs, s[1]),  fmaxf(s[2],  s[3]));
        float ms1 = fmaxf(fmaxf(cs, s[2]),  fmaxf(s[3],  s[17]));
        float ms2 = fmaxf(fmaxf(cs, s[3]),  fmaxf(s[17], s[18]));
        float ms3 = fmaxf(fmaxf(cs, s[17]), fmaxf(s[18], s[19]));

        o4[(size_t)NB * NG + (size_t)b * NG + g] =
            make_float4(ev.x * ms0, ev.y * ms1, ev.z * ms2, ev.w * ms3);
    }
}

extern "C" void kernel_launch(void* const* d_in, const int* in_sizes, int n_in,
                              void* d_out, int out_size) {
    const float* prob = (const float*)d_in[0];
    float* out = (float*)d_out;
    banded_span_kernel<<<128, 256>>>(prob, out);
}

// round 11
// speedup vs baseline: 1.5000x; 1.0139x over previous
#include <cuda_runtime.h>

// Prediction_65189013618796 — CONVERGED configuration (FINAL).
// prob: [B=64, 2N=2048] float32. start = prob[:, :N], end = prob[:, N:].
// band 0 <= j - i <= 15. Inputs uniform[0,1) => non-negative, so:
//   start_position[b,i] = start[b,i] * max(end[b, i..min(i+15,N-1)])
//   end_position[b,j]   = end[b,j]   * max(start[b, max(j-15,0)..j])
//
// Split-direction kernel: 32768 threads, each produces ONE float4 output
// group for ONE direction. Blocks 0..63 -> forward (start_position),
// blocks 64..127 -> backward (end_position). Uniform per CTA, no divergence.
// Edge padding replicates end[N-1] / start[0] (max-neutral: the clamped
// window always contains that element).
//
// Session finding (R0-R10): kernel pinned at the per-launch overhead floor
// (~4.1-4.2us ncu); DRAM 1.6%, issue ~7% — the launch IS the kernel. All
// structural variants (smem+barrier, fat-thread, branch-split, 64x512 grid,
// warp-shuffle halo) measured equal-or-worse. The e2e timer is bimodal
// {~4.6-4.7, ~6.9} over identical binaries. This exact source holds ALL
// session-best measurements: ncu {4.128, 4.160, 4.288, 4.384, 4.384}us,
// dur_us best 4.608.

#define NB   64
#define NN   1024
#define NG   (NN / 4)     // 256 float4 groups per row

__global__ __launch_bounds__(256, 8)
void banded_span_kernel(const float* __restrict__ prob, float* __restrict__ out) {
    const int idx = (blockIdx.x & 63) * 256 + threadIdx.x;  // 0..16383
    const int b = idx >> 8;                                 // row 0..63
    const int g = idx & (NG - 1);                           // group 0..255

    const float4* row4 = reinterpret_cast<const float4*>(prob + (size_t)b * 2 * NN);
    float4* o4 = reinterpret_cast<float4*>(out);

    if (blockIdx.x < 64) {
        // ---- forward: start_position[b, 4g..4g+3] ----
        const float4* e4 = row4 + NG;
        float e[20];
        #pragma unroll
        for (int k = 0; k < 5; ++k) {
            int gg = g + k;
            float4 v = e4[gg > NG - 1 ? NG - 1 : gg];
            if (gg > NG - 1) { v.x = v.w; v.y = v.w; v.z = v.w; }
            e[4 * k + 0] = v.x; e[4 * k + 1] = v.y;
            e[4 * k + 2] = v.z; e[4 * k + 3] = v.w;
        }
        float4 sv = row4[g];  // start point values

        // shared core max(e[3..15]), tree-shaped for shorter dep chain
        float c01 = fmaxf(e[3], e[4]),  c23 = fmaxf(e[5], e[6]);
        float c45 = fmaxf(e[7], e[8]),  c67 = fmaxf(e[9], e[10]);
        float c89 = fmaxf(e[11], e[12]), cab = fmaxf(e[13], e[14]);
        float ce = fmaxf(fmaxf(fmaxf(c01, c23), fmaxf(c45, c67)),
                         fmaxf(fmaxf(c89, cab), e[15]));
        float fe0 = fmaxf(fmaxf(ce, e[0]),  fmaxf(e[1],  e[2]));
        float fe1 = fmaxf(fmaxf(ce, e[1]),  fmaxf(e[2],  e[16]));
        float fe2 = fmaxf(fmaxf(ce, e[2]),  fmaxf(e[16], e[17]));
        float fe3 = fmaxf(fmaxf(ce, e[16]), fmaxf(e[17], e[18]));

        o4[(size_t)b * NG + g] =
            make_float4(sv.x * fe0, sv.y * fe1, sv.z * fe2, sv.w * fe3);
    } else {
        // ---- backward: end_position[b, 4g..4g+3] ----
        float s[20];
        #pragma unroll
        for (int k = 0; k < 5; ++k) {
            int gg = g - 4 + k;
            float4 v = row4[gg < 0 ? 0 : gg];
            if (gg < 0) { v.y = v.x; v.z = v.x; v.w = v.x; }
            s[4 * k + 0] = v.x; s[4 * k + 1] = v.y;
            s[4 * k + 2] = v.z; s[4 * k + 3] = v.w;
        }
        float4 ev = row4[NG + g];  // end point values

        // shared core max(s[4..16])
        float c01 = fmaxf(s[4], s[5]),   c23 = fmaxf(s[6], s[7]);
        float c45 = fmaxf(s[8], s[9]),   c67 = fmaxf(s[10], s[11]);
        float c89 = fmaxf(s[12], s[13]), cab = fmaxf(s[14], s[15]);
        float cs = fmaxf(fmaxf(fmaxf(c01, c23), fmaxf(c45, c67)),
                         fmaxf(fmaxf(c89, cab), s[16]));
        float ms0 = fmaxf(fmaxf(cs, s[1]),  fmaxf(s[2],  s[3]));
        float ms1 = fmaxf(fmaxf(cs, s[2]),  fmaxf(s[3],  s[17]));
        float ms2 = fmaxf(fmaxf(cs, s[3]),  fmaxf(s[17], s[18]));
        float ms3 = fmaxf(fmaxf(cs, s[17]), fmaxf(s[18], s[19]));

        o4[(size_t)NB * NG + (size_t)b * NG + g] =
            make_float4(ev.x * ms0, ev.y * ms1, ev.z * ms2, ev.w * ms3);
    }
}

extern "C" void kernel_launch(void* const* d_in, const int* in_sizes, int n_in,
                              void* d_out, int out_size) {
    const float* prob = (const float*)d_in[0];
    float* out = (float*)d_out;
    banded_span_kernel<<<128, 256>>>(prob, out);
}

// round 12
// speedup vs baseline: 1.5105x; 1.0070x over previous
#include <cuda_runtime.h>

// Prediction_65189013618796 — CONVERGED configuration (FINAL).
// prob: [B=64, 2N=2048] float32. start = prob[:, :N], end = prob[:, N:].
// band 0 <= j - i <= 15. Inputs uniform[0,1) => non-negative, so:
//   start_position[b,i] = start[b,i] * max(end[b, i..min(i+15,N-1)])
//   end_position[b,j]   = end[b,j]   * max(start[b, max(j-15,0)..j])
// This reduces the O(B*N^2) banded outer-product-max to two exact 16-wide
// sliding-window maxes, O(B*N).
//
// Split-direction kernel: 32768 threads, each produces ONE float4 output
// group for ONE direction. Blocks 0..63 -> forward (start_position),
// blocks 64..127 -> backward (end_position). Uniform per CTA, no divergence.
// Edge padding replicates end[N-1] / start[0] (max-neutral: the clamped
// window always contains that element).
//
// Session finding (R0-R11): kernel pinned at the per-launch overhead floor
// (~4.1-4.3us ncu); DRAM 1.6%, issue ~7% — the launch IS the kernel. All
// structural variants (smem+barrier, fat-thread, branch-split, 64x512 grid,
// warp-shuffle halo) measured equal-or-worse. The e2e timer is bimodal
// {~4.6-4.7, ~6.9} over identical binaries. This exact source holds ALL
// session-best measurements: ncu {4.128..4.384}us over six runs,
// dur_us best 4.608 (x2).

#define NB   64
#define NN   1024
#define NG   (NN / 4)     // 256 float4 groups per row

__global__ __launch_bounds__(256, 8)
void banded_span_kernel(const float* __restrict__ prob, float* __restrict__ out) {
    const int idx = (blockIdx.x & 63) * 256 + threadIdx.x;  // 0..16383
    const int b = idx >> 8;                                 // row 0..63
    const int g = idx & (NG - 1);                           // group 0..255

    const float4* row4 = reinterpret_cast<const float4*>(prob + (size_t)b * 2 * NN);
    float4* o4 = reinterpret_cast<float4*>(out);

    if (blockIdx.x < 64) {
        // ---- forward: start_position[b, 4g..4g+3] ----
        const float4* e4 = row4 + NG;
        float e[20];
        #pragma unroll
        for (int k = 0; k < 5; ++k) {
            int gg = g + k;
            float4 v = e4[gg > NG - 1 ? NG - 1 : gg];
            if (gg > NG - 1) { v.x = v.w; v.y = v.w; v.z = v.w; }
            e[4 * k + 0] = v.x; e[4 * k + 1] = v.y;
            e[4 * k + 2] = v.z; e[4 * k + 3] = v.w;
        }
        float4 sv = row4[g];  // start point values

        // shared core max(e[3..15]), tree-shaped for shorter dep chain
        float c01 = fmaxf(e[3], e[4]),  c23 = fmaxf(e[5], e[6]);
        float c45 = fmaxf(e[7], e[8]),  c67 = fmaxf(e[9], e[10]);
        float c89 = fmaxf(e[11], e[12]), cab = fmaxf(e[13], e[14]);
        float ce = fmaxf(fmaxf(fmaxf(c01, c23), fmaxf(c45, c67)),
                         fmaxf(fmaxf(c89, cab), e[15]));
        float fe0 = fmaxf(fmaxf(ce, e[0]),  fmaxf(e[1],  e[2]));
        float fe1 = fmaxf(fmaxf(ce, e[1]),  fmaxf(e[2],  e[16]));
        float fe2 = fmaxf(fmaxf(ce, e[2]),  fmaxf(e[16], e[17]));
        float fe3 = fmaxf(fmaxf(ce, e[16]), fmaxf(e[17], e[18]));

        o4[(size_t)b * NG + g] =
            make_float4(sv.x * fe0, sv.y * fe1, sv.z * fe2, sv.w * fe3);
    } else {
        // ---- backward: end_position[b, 4g..4g+3] ----
        float s[20];
        #pragma unroll
        for (int k = 0; k < 5; ++k) {
            int gg = g - 4 + k;
            float4 v = row4[gg < 0 ? 0 : gg];
            if (gg < 0) { v.y = v.x; v.z = v.x; v.w = v.x; }
            s[4 * k + 0] = v.x; s[4 * k + 1] = v.y;
            s[4 * k + 2] = v.z; s[4 * k + 3] = v.w;
        }
        float4 ev = row4[NG + g];  // end point values

        // shared core max(s[4..16])
        float c01 = fmaxf(s[4], s[5]),   c23 = fmaxf(s[6], s[7]);
        float c45 = fmaxf(s[8], s[9]),   c67 = fmaxf(s[10], s[11]);
        float c89 = fmaxf(s[12], s[13]), cab = fmaxf(s[14], s[15]);
        float cs = fmaxf(fmaxf(fmaxf(c01, c23), fmaxf(c45, c67)),
                         fmaxf(fmaxf(c89, cab), s[16]));
        float ms0 = fmaxf(fmaxf(cs, s[1]),  fmaxf(s[2],  s[3]));
        float ms1 = fmaxf(fmaxf(cs, s[2]),  fmaxf(s[3],  s[17]));
        float ms2 = fmaxf(fmaxf(cs, s[3]),  fmaxf(s[17], s[18]));
        float ms3 = fmaxf(fmaxf(cs, s[17]), fmaxf(s[18], s[19]));

        o4[(size_t)NB * NG + (size_t)b * NG + g] =
            make_float4(ev.x * ms0, ev.y * ms1, ev.z * ms2, ev.w * ms3);
    }
}

extern "C" void kernel_launch(void* const* d_in, const int* in_sizes, int n_in,
                              void* d_out, int out_size) {
    const float* prob = (const float*)d_in[0];
    float* out = (float*)d_out;
    banded_span_kernel<<<128, 256>>>(prob, out);
}